// round 7
// baseline (speedup 1.0000x reference)
#include <cuda_runtime.h>
#include <cstdint>

#define TABLE_N  262144
#define TILE_PTS 1024
#define NTHREADS 256

// Packed (weight, bias) table — static __device__ scratch, rebuilt every call.
__device__ __align__(16) float2 g_wb[TABLE_N];

static __device__ __forceinline__ uint32_t smem_u32(const void* p) {
    return (uint32_t)__cvta_generic_to_shared(p);
}

__global__ void __launch_bounds__(256)
pack_wb_kernel(const float4* __restrict__ w4, const float4* __restrict__ b4)
{
    int i = blockIdx.x * blockDim.x + threadIdx.x;   // [0, TABLE_N/4)
    if (i >= TABLE_N / 4) return;
    float4 w = w4[i];
    float4 b = b4[i];
    float4* dst = reinterpret_cast<float4*>(&g_wb[4 * i]);
    dst[0] = make_float4(w.x, b.x, w.y, b.y);
    dst[1] = make_float4(w.z, b.z, w.w, b.w);
}

__device__ __forceinline__ unsigned part1by1(unsigned x) {
    x &= 0x0000ffffu;
    x = (x | (x << 8)) & 0x00FF00FFu;
    x = (x | (x << 4)) & 0x0F0F0F0Fu;
    x = (x | (x << 2)) & 0x33333333u;
    x = (x | (x << 1)) & 0x55555555u;
    return x;
}

// XLA-lowered index path: divide-by-constant == multiply by f32 reciprocal.
__device__ __forceinline__ int quad_index(float px, float py) {
    const float SCALE   = 10000000.0f;
    const float R_SCALE = 1.0f / 10000000.0f;
    const float R_W     = 1.0f / 360.0f;
    const float R_H     = 1.0f / 180.0f;
    float cx = __fmul_rn(rintf(__fmul_rn(px, SCALE)), R_SCALE);
    float cy = __fmul_rn(rintf(__fmul_rn(py, SCALE)), R_SCALE);
    float u  = __fmul_rn(__fadd_rn(cx, 180.0f), R_W);
    float v  = __fmul_rn(__fadd_rn(cy,  90.0f), R_H);
    int ix = (int)__fmul_rn(u, 512.0f);
    int iy = (int)__fmul_rn(v, 512.0f);
    ix = min(max(ix, 0), 511);
    iy = min(max(iy, 0), 511);
    return (int)(part1by1((unsigned)ix) | (part1by1((unsigned)iy) << 1));
}

// One 1024-point tile per CTA. Streaming I/O staged through SMEM via bulk-async
// (TMA engine) so the L1tex global pipeline carries ONLY the gathers.
__global__ void __launch_bounds__(NTHREADS)
quadpool_tma_kernel(const float* __restrict__ in,   // [n,2]
                    const float* __restrict__ x,    // [n]
                    float* __restrict__ out)        // [n]
{
    __shared__ __align__(128) float4 s_coords[TILE_PTS / 2]; // 8 KB
    __shared__ __align__(128) float4 s_x[TILE_PTS / 4];      // 4 KB
    __shared__ __align__(128) float4 s_out[TILE_PTS / 4];    // 4 KB
    __shared__ __align__(8)  unsigned long long s_mbar;

    const int tid = threadIdx.x;
    const long long base = (long long)blockIdx.x * TILE_PTS;

    const uint32_t mbar    = smem_u32(&s_mbar);
    const uint32_t d_coord = smem_u32(s_coords);
    const uint32_t d_x     = smem_u32(s_x);
    const uint32_t d_o     = smem_u32(s_out);

    if (tid == 0) {
        asm volatile("mbarrier.init.shared.b64 [%0], 1;" :: "r"(mbar) : "memory");
        asm volatile("fence.proxy.async.shared::cta;" ::: "memory");
    }
    __syncthreads();

    if (tid == 0) {
        const uint32_t total_tx = TILE_PTS * 8 + TILE_PTS * 4;  // 12288 B
        asm volatile("mbarrier.arrive.expect_tx.shared.b64 _, [%0], %1;"
                     :: "r"(mbar), "r"(total_tx) : "memory");
        asm volatile(
            "cp.async.bulk.shared::cta.global.mbarrier::complete_tx::bytes [%0], [%1], %2, [%3];"
            :: "r"(d_coord), "l"(in + base * 2), "r"((uint32_t)(TILE_PTS * 8)), "r"(mbar)
            : "memory");
        asm volatile(
            "cp.async.bulk.shared::cta.global.mbarrier::complete_tx::bytes [%0], [%1], %2, [%3];"
            :: "r"(d_x), "l"(x + base), "r"((uint32_t)(TILE_PTS * 4)), "r"(mbar)
            : "memory");
    }

    // Wait for both bulk loads (phase parity 0; single-shot barrier).
    asm volatile(
        "{\n\t"
        ".reg .pred P;\n\t"
        "WAIT_%=:\n\t"
        "mbarrier.try_wait.parity.acquire.cta.shared::cta.b64 P, [%0], 0, 0x989680;\n\t"
        "@!P bra WAIT_%=;\n\t"
        "}"
        :: "r"(mbar) : "memory");

    float4 p01 = s_coords[2 * tid];
    float4 p23 = s_coords[2 * tid + 1];
    float4 xv  = s_x[tid];

    int i0 = quad_index(p01.x, p01.y);
    int i1 = quad_index(p01.z, p01.w);
    int i2 = quad_index(p23.x, p23.y);
    int i3 = quad_index(p23.z, p23.w);

    float2 wb0 = g_wb[i0];
    float2 wb1 = g_wb[i1];
    float2 wb2 = g_wb[i2];
    float2 wb3 = g_wb[i3];

    float4 o;
    o.x = fmaf(wb0.x, xv.x, wb0.y);
    o.y = fmaf(wb1.x, xv.y, wb1.y);
    o.z = fmaf(wb2.x, xv.z, wb2.y);
    o.w = fmaf(wb3.x, xv.w, wb3.y);
    s_out[tid] = o;

    __syncthreads();
    asm volatile("fence.proxy.async.shared::cta;" ::: "memory");

    if (tid == 0) {
        asm volatile(
            "cp.async.bulk.global.shared::cta.bulk_group [%0], [%1], %2;"
            :: "l"(out + base), "r"(d_o), "r"((uint32_t)(TILE_PTS * 4))
            : "memory");
        asm volatile("cp.async.bulk.commit_group;" ::: "memory");
        asm volatile("cp.async.bulk.wait_group 0;" ::: "memory");
    }
}

// Scalar tail for n % 1024 (direct global loads; tiny).
__global__ void quadpool_tail_kernel(const float2* __restrict__ in2,
                                     const float*  __restrict__ x,
                                     float* __restrict__ out,
                                     int start, int n)
{
    int i = start + blockIdx.x * blockDim.x + threadIdx.x;
    if (i >= n) return;
    float2 p = in2[i];
    float2 wb = g_wb[quad_index(p.x, p.y)];
    out[i] = fmaf(wb.x, x[i], wb.y);
}

extern "C" void kernel_launch(void* const* d_in, const int* in_sizes, int n_in,
                              void* d_out, int out_size)
{
    const float* in  = (const float*)d_in[0];   // [N,2]
    const float* x   = (const float*)d_in[1];   // [N]
    const float* w   = (const float*)d_in[2];   // [262144]
    const float* b   = (const float*)d_in[3];   // [262144]
    float* out = (float*)d_out;

    pack_wb_kernel<<<TABLE_N / 4 / 256, 256>>>((const float4*)w, (const float4*)b);

    int n = in_sizes[1];
    int tiles = n / TILE_PTS;
    if (tiles > 0) {
        quadpool_tma_kernel<<<tiles, NTHREADS>>>(in, x, out);
    }
    int done = tiles * TILE_PTS;
    int rem = n - done;
    if (rem > 0) {
        quadpool_tail_kernel<<<(rem + 255) / 256, 256>>>(
            (const float2*)in, x, out, done, n);
    }
}

// round 11
// speedup vs baseline: 1.1882x; 1.1882x over previous
#include <cuda_runtime.h>
#include <cstdint>

#define TABLE_N  262144
#define NTHREADS 256
#define PPT      8                     // points per thread
#define CTA_PTS  (NTHREADS * PPT)      // 2048

// Packed (weight, bias) table — static __device__ scratch, rebuilt every call.
__device__ __align__(16) float2 g_wb[TABLE_N];

__global__ void __launch_bounds__(256)
pack_wb_kernel(const float4* __restrict__ w4, const float4* __restrict__ b4)
{
    int i = blockIdx.x * blockDim.x + threadIdx.x;   // [0, TABLE_N/4)
    if (i >= TABLE_N / 4) return;
    float4 w = w4[i];
    float4 b = b4[i];
    float4* dst = reinterpret_cast<float4*>(&g_wb[4 * i]);
    dst[0] = make_float4(w.x, b.x, w.y, b.y);
    dst[1] = make_float4(w.z, b.z, w.w, b.w);
}

__device__ __forceinline__ unsigned part1by1(unsigned x) {
    x &= 0x0000ffffu;
    x = (x | (x << 8)) & 0x00FF00FFu;
    x = (x | (x << 4)) & 0x0F0F0F0Fu;
    x = (x | (x << 2)) & 0x33333333u;
    x = (x | (x << 1)) & 0x55555555u;
    return x;
}

// XLA-lowered index path: divide-by-constant == multiply by f32 reciprocal.
// All ops pinned to IEEE rn intrinsics; rintf == round-half-even; C cast ==
// truncate toward zero.
__device__ __forceinline__ int quad_index(float px, float py) {
    const float SCALE   = 10000000.0f;
    const float R_SCALE = 1.0f / 10000000.0f;
    const float R_W     = 1.0f / 360.0f;
    const float R_H     = 1.0f / 180.0f;
    float cx = __fmul_rn(rintf(__fmul_rn(px, SCALE)), R_SCALE);
    float cy = __fmul_rn(rintf(__fmul_rn(py, SCALE)), R_SCALE);
    float u  = __fmul_rn(__fadd_rn(cx, 180.0f), R_W);
    float v  = __fmul_rn(__fadd_rn(cy,  90.0f), R_H);
    int ix = (int)__fmul_rn(u, 512.0f);
    int iy = (int)__fmul_rn(v, 512.0f);
    ix = min(max(ix, 0), 511);
    iy = min(max(iy, 0), 511);
    return (int)(part1by1((unsigned)ix) | (part1by1((unsigned)iy) << 1));
}

// 8 points/thread, lane-contiguous strided layout:
// thread t of CTA c handles points c*2048 + t + j*256, j = 0..7.
// Streaming loads/stores are perfectly coalesced; gathers are the only
// irregular traffic (1 L1 wavefront per point, 8 in flight per thread).
__global__ void __launch_bounds__(NTHREADS)
quadpool_kernel(const float2* __restrict__ in2,  // [n]
                const float*  __restrict__ x,    // [n]
                float*        __restrict__ out)  // [n]
{
    const int base = blockIdx.x * CTA_PTS + threadIdx.x;

    // Streaming coord loads (evict-first: keep L1 for the gather table).
    float2 p[PPT];
#pragma unroll
    for (int j = 0; j < PPT; j++)
        p[j] = __ldcs(&in2[base + j * NTHREADS]);

    // Streaming x loads.
    float xv[PPT];
#pragma unroll
    for (int j = 0; j < PPT; j++)
        xv[j] = __ldcs(&x[base + j * NTHREADS]);

    // Indices.
    int idx[PPT];
#pragma unroll
    for (int j = 0; j < PPT; j++)
        idx[j] = quad_index(p[j].x, p[j].y);

    // 8 independent gathers in flight.
    float2 wb[PPT];
#pragma unroll
    for (int j = 0; j < PPT; j++)
        wb[j] = __ldg(&g_wb[idx[j]]);

#pragma unroll
    for (int j = 0; j < PPT; j++)
        out[base + j * NTHREADS] = fmaf(wb[j].x, xv[j], wb[j].y);
}

// Scalar tail for n % 2048 (not expected for N = 8388608, but safe).
__global__ void quadpool_tail_kernel(const float2* __restrict__ in2,
                                     const float*  __restrict__ x,
                                     float* __restrict__ out,
                                     int start, int n)
{
    int i = start + blockIdx.x * blockDim.x + threadIdx.x;
    if (i >= n) return;
    float2 pt = in2[i];
    float2 wb = __ldg(&g_wb[quad_index(pt.x, pt.y)]);
    out[i] = fmaf(wb.x, x[i], wb.y);
}

extern "C" void kernel_launch(void* const* d_in, const int* in_sizes, int n_in,
                              void* d_out, int out_size)
{
    const float* in  = (const float*)d_in[0];   // [N,2]
    const float* x   = (const float*)d_in[1];   // [N]
    const float* w   = (const float*)d_in[2];   // [262144]
    const float* b   = (const float*)d_in[3];   // [262144]
    float* out = (float*)d_out;

    pack_wb_kernel<<<TABLE_N / 4 / 256, 256>>>((const float4*)w, (const float4*)b);

    int n = in_sizes[1];
    int tiles = n / CTA_PTS;
    if (tiles > 0) {
        quadpool_kernel<<<tiles, NTHREADS>>>((const float2*)in, x, out);
    }
    int done = tiles * CTA_PTS;
    int rem = n - done;
    if (rem > 0) {
        quadpool_tail_kernel<<<(rem + 255) / 256, 256>>>(
            (const float2*)in, x, out, done, n);
    }
}